// round 15
// baseline (speedup 1.0000x reference)
#include <cuda_runtime.h>
#include <cuda_bf16.h>

// Resample2d bilinear warp — direct scalar gather, finer channel split.
// input1: [8,64,384,512] f32, input2(flow): [8,2,384,512] f32, out NCHW f32.
//
// R2-R13 established: divergent-gather l1tex wavefronts are the floor; all
// staging alternatives cost more. R14 (16ch/block split + __stcs) = 207.6us,
// L1 util 88%. This round: DCH=8 (49152 blocks, ~2us each) for finer wave-
// tail smoothing. Flow re-reads (8x) stay L2-resident (12.6MB << 126MB L2),
// so DRAM traffic is ~unchanged; extra L1 cost ~0.16 cyc/warp-channel.

#define B_ 8
#define D_ 64
#define H_ 384
#define W_ 512
#define PLANE_ (H_ * W_)
#define TPB 256
#define DCH 8                  // channels per block
#define DSPLIT (D_ / DCH)      // 8

__global__ __launch_bounds__(TPB)
void resample2d_kernel(const float* __restrict__ img,
                       const float* __restrict__ flow,
                       float* __restrict__ out)
{
    // blockIdx.x = ((b*H + h)*WCHUNKS + wc)*DSPLIT + ds
    int bid = blockIdx.x;
    const int ds = bid & (DSPLIT - 1);
    bid >>= 3;
    const int wc = bid & 1;                  // W/TPB = 2
    bid >>= 1;
    const int h = bid % H_;
    const int b = bid / H_;
    const int w = wc * TPB + threadIdx.x;
    const int d0 = ds * DCH;

    // flow [B,2,H,W]
    const unsigned foff = (unsigned)b * (2u * PLANE_) + (unsigned)h * W_ + w;
    const float u = __ldg(flow + foff);
    const float v = __ldg(flow + foff + PLANE_);

    float fx = (float)w + u;
    float fy = (float)h + v;
    fx = fminf(fmaxf(fx, 0.0f), (float)(W_ - 1));
    fy = fminf(fmaxf(fy, 0.0f), (float)(H_ - 1));
    const int x0 = min((int)fx, W_ - 2);
    const int y0 = min((int)fy, H_ - 2);
    const float wx = fx - (float)x0;
    const float wy = fy - (float)y0;

    const float w00 = (1.0f - wy) * (1.0f - wx);
    const float w01 = (1.0f - wy) * wx;
    const float w10 = wy * (1.0f - wx);
    const float w11 = wy * wx;

    // 32-bit element offsets (tensor = 100.6M elems < 2^31)
    unsigned o0 = (unsigned)b * (D_ * PLANE_) + (unsigned)d0 * PLANE_
                + (unsigned)y0 * W_ + (unsigned)x0;
    unsigned o1 = o0 + W_;
    unsigned oo = (unsigned)b * (D_ * PLANE_) + (unsigned)d0 * PLANE_
                + (unsigned)h * W_ + (unsigned)w;

    #pragma unroll
    for (int d = 0; d < DCH; ++d) {
        const float a00 = __ldg(img + o0);
        const float a01 = __ldg(img + o0 + 1);
        const float a10 = __ldg(img + o1);
        const float a11 = __ldg(img + o1 + 1);
        float r = w00 * a00;
        r = fmaf(w01, a01, r);
        r = fmaf(w10, a10, r);
        r = fmaf(w11, a11, r);
        __stcs(out + oo, r);
        o0 += PLANE_;
        o1 += PLANE_;
        oo += PLANE_;
    }
}

extern "C" void kernel_launch(void* const* d_in, const int* in_sizes, int n_in,
                              void* d_out, int out_size)
{
    const float* img  = (const float*)d_in[0];
    const float* flow = (const float*)d_in[1];
    float* out = (float*)d_out;

    dim3 grid(B_ * H_ * (W_ / TPB) * DSPLIT);   // 8*384*2*8 = 49152
    dim3 block(TPB);
    resample2d_kernel<<<grid, block>>>(img, flow, out);
}